// round 10
// baseline (speedup 1.0000x reference)
#include <cuda_runtime.h>
#include <cstdint>

// Problem constants
#define TOK 8192      // b*n tokens
#define D   1024
#define H   8
#define E   16
#define CS  2048
#define COLS (H*E)     // 128 projection columns
#define CPAIR (COLS/2) // 64 column pairs
#define NCP (CS/2)     // 1024 code pairs per head

typedef unsigned long long u64;

// -------- device scratch (static; no allocations allowed) --------
__device__ float g_S[COLS];                           // column sums of W
__device__ __align__(16) float2 g_Wp[D * CPAIR];      // W' = W - S/D, [d][colpair]      (512 KB)
__device__ __align__(16) float2 g_cbp[H * NCP * E];   // normalized cb, code-pair packed (1 MB)
__device__ __align__(16) float  g_P[TOK * COLS];      // projections [t][h*16+e]         (4 MB)
__device__ float g_bestp[2][TOK * H];                 // partial argmax: best score
__device__ int   g_idxp[2][TOK * H];                  // partial argmax: index

// -------- f32x2 helpers --------
__device__ __forceinline__ u64 pk2(float lo, float hi) {
    u64 r; asm("mov.b64 %0, {%1,%2};" : "=l"(r) : "f"(lo), "f"(hi)); return r;
}
__device__ __forceinline__ void upk2(float& lo, float& hi, u64 v) {
    asm("mov.b64 {%0,%1}, %2;" : "=f"(lo), "=f"(hi) : "l"(v));
}
#define FMA2(acc, a, b) asm("fma.rn.f32x2 %0, %1, %2, %0;" : "+l"(acc) : "l"(a), "l"(b))
#define ADD2(d, a, b)   asm("add.rn.f32x2 %0, %1, %2;" : "=l"(d) : "l"(a), "l"(b))

// -------- 1: column sums S[h,e] = sum_d W[h,d,e] --------
__global__ void prepS_kernel(const float* __restrict__ W) {
    int col = blockIdx.x;            // h*16+e, 128 blocks
    int h = col >> 4, e = col & 15;
    float s = 0.f;
    for (int d = threadIdx.x; d < D; d += 256)
        s += W[(h * D + d) * E + e];
    __shared__ float red[256];
    red[threadIdx.x] = s;
    __syncthreads();
    for (int off = 128; off > 0; off >>= 1) {
        if (threadIdx.x < off) red[threadIdx.x] += red[threadIdx.x + off];
        __syncthreads();
    }
    if (threadIdx.x == 0) g_S[col] = red[0];
}

// -------- 2: W'[d][cp] = (W - S/D) packed as column-pairs --------
__global__ void prepW_kernel(const float* __restrict__ W) {
    int i = blockIdx.x * 256 + threadIdx.x;   // 65536 = D*CPAIR
    int d = i >> 6, cp = i & 63;
    int h = cp >> 3, ep = cp & 7;
    const float invD = 1.0f / 1024.0f;
    float w0 = W[(h * D + d) * E + 2 * ep]     - g_S[h * E + 2 * ep]     * invD;
    float w1 = W[(h * D + d) * E + 2 * ep + 1] - g_S[h * E + 2 * ep + 1] * invD;
    g_Wp[i] = make_float2(w0, w1);
}

// -------- 3: normalized codebook, code-pair packed --------
__global__ void prepCB_kernel(const float* __restrict__ CB) {
    int i = blockIdx.x * 256 + threadIdx.x;   // 8192 = H*NCP
    const float4* a4 = (const float4*)(CB + (size_t)i * 2 * E);
    float4 va[4], vb[4];
#pragma unroll
    for (int k = 0; k < 4; ++k) va[k] = a4[k];
#pragma unroll
    for (int k = 0; k < 4; ++k) vb[k] = a4[4 + k];
    float sa = 0.f, sb = 0.f;
#pragma unroll
    for (int k = 0; k < 4; ++k) {
        sa += va[k].x * va[k].x + va[k].y * va[k].y + va[k].z * va[k].z + va[k].w * va[k].w;
        sb += vb[k].x * vb[k].x + vb[k].y * vb[k].y + vb[k].z * vb[k].z + vb[k].w * vb[k].w;
    }
    float ra = 1.0f / sqrtf(sa + 1e-12f);
    float rb = 1.0f / sqrtf(sb + 1e-12f);
    float2* out = g_cbp + (size_t)i * E;
    const float* a = (const float*)va;
    const float* b = (const float*)vb;
#pragma unroll
    for (int e = 0; e < E; ++e)
        out[e] = make_float2(a[e] * ra, b[e] * rb);
}

// -------- 4: projection GEMM, f32x2, reg-prefetch, 512 CTAs x 128 thr ----
// CTA: 16 tokens, all 64 colpairs. Thread (tg = tid>>4 -> tokens tg, tg+8;
// cg4 = tid&15 -> colpairs 4cg4..4cg4+3). Per dd: 8 FMA2 : 4 LDS.
__global__ __launch_bounds__(128) void proj_kernel(const float* __restrict__ x) {
    __shared__ u64    xs[16][34];   // [tok][dd] dup (x,x); pad 34
    __shared__ float2 Ws[32][64];   // [dd][colpair], 16 KB
    int t0 = blockIdx.x * 16;
    int tid = threadIdx.x;
    int tg  = tid >> 4;             // 0..7 -> tokens tg, tg+8
    int cg4 = tid & 15;             // 0..15 -> colpairs 4cg4..+3

    // staging addresses (constant across chunks)
    int xtok = tid >> 3;            // token staged by this thread (0..15)
    int xf4  = tid & 7;             // float4 slot within 32-dd chunk (dd=4*xf4..)
    const float4* xrow = (const float4*)(x + (size_t)(t0 + xtok) * D);

    u64 acc[2][4];
#pragma unroll
    for (int i = 0; i < 2; ++i)
#pragma unroll
        for (int k = 0; k < 4; ++k) acc[i][k] = 0ull;

    float4 px;
    ulonglong2 pw[8];

    // prefetch chunk 0
    px = xrow[xf4];
#pragma unroll
    for (int j = 0; j < 8; ++j) {
        int q = j * 128 + tid;       // 0..1023
        int dd = q >> 5, c2 = q & 31;
        pw[j] = *(const ulonglong2*)&g_Wp[(size_t)dd * CPAIR + 2 * c2];
    }

    for (int ch = 0; ch < 32; ++ch) {
        if (ch > 0) __syncthreads();     // prev chunk consumed
        // store prefetched chunk
        {
            int d0 = 4 * xf4;
            xs[xtok][d0 + 0] = pk2(px.x, px.x);
            xs[xtok][d0 + 1] = pk2(px.y, px.y);
            xs[xtok][d0 + 2] = pk2(px.z, px.z);
            xs[xtok][d0 + 3] = pk2(px.w, px.w);
#pragma unroll
            for (int j = 0; j < 8; ++j) {
                int q = j * 128 + tid;
                int dd = q >> 5, c2 = q & 31;
                *(ulonglong2*)&Ws[dd][2 * c2] = pw[j];
            }
        }
        __syncthreads();
        // prefetch next chunk (hidden under compute)
        if (ch < 31) {
            int base = (ch + 1) * 32;
            px = xrow[(base >> 2) + xf4];
#pragma unroll
            for (int j = 0; j < 8; ++j) {
                int q = j * 128 + tid;
                int dd = q >> 5, c2 = q & 31;
                pw[j] = *(const ulonglong2*)&g_Wp[(size_t)(base + dd) * CPAIR + 2 * c2];
            }
        }
        // compute
#pragma unroll 4
        for (int dd = 0; dd < 32; ++dd) {
            ulonglong2 w0 = *(const ulonglong2*)&Ws[dd][4 * cg4];
            ulonglong2 w1 = *(const ulonglong2*)&Ws[dd][4 * cg4 + 2];
#pragma unroll
            for (int i = 0; i < 2; ++i) {
                u64 xv = xs[tg + 8 * i][dd];
                FMA2(acc[i][0], w0.x, xv);
                FMA2(acc[i][1], w0.y, xv);
                FMA2(acc[i][2], w1.x, xv);
                FMA2(acc[i][3], w1.y, xv);
            }
        }
    }
#pragma unroll
    for (int i = 0; i < 2; ++i) {
        float4 o0, o1;
        upk2(o0.x, o0.y, acc[i][0]);
        upk2(o0.z, o0.w, acc[i][1]);
        upk2(o1.x, o1.y, acc[i][2]);
        upk2(o1.z, o1.w, acc[i][3]);
        float* dst = &g_P[(size_t)(t0 + tg + 8 * i) * COLS + 8 * cg4];
        *(float4*)dst = o0;
        *(float4*)(dst + 4) = o1;
    }
}

// -------- 5: similarity scan, code-chunk split, smem broadcast ------------
// Grid: 512 CTAs = 32 token-tiles (256 tok) x 8 heads x 2 code chunks.
// 128 thr, T=2 tokens/thread. Each CTA scans 512 code pairs (1024 codes) in
// 4 sub-chunks of 128 pairs (16 KB smem); pair index warp-uniform -> broadcast.
// Writes partial (best, idx) to its own slot; reduce_kernel merges.
__global__ __launch_bounds__(128) void sim_kernel() {
    __shared__ ulonglong2 cbs[1024];      // 16 KB
    int tid = threadIdx.x;
    int b = blockIdx.x;
    int cc = b & 1;                       // code chunk (512 pairs)
    int h = (b >> 1) & 7;
    int tb = b >> 4;                      // 0..31
    int t0 = tb * 256 + tid * 2;

    u64 qd0[16], qd1[16];
    {
        const float4* q4 = (const float4*)&g_P[(size_t)t0 * COLS + h * E];
#pragma unroll
        for (int k = 0; k < 4; ++k) {
            float4 v = q4[k];
            qd0[4 * k + 0] = pk2(v.x, v.x);
            qd0[4 * k + 1] = pk2(v.y, v.y);
            qd0[4 * k + 2] = pk2(v.z, v.z);
            qd0[4 * k + 3] = pk2(v.w, v.w);
        }
        q4 = (const float4*)&g_P[(size_t)(t0 + 1) * COLS + h * E];
#pragma unroll
        for (int k = 0; k < 4; ++k) {
            float4 v = q4[k];
            qd1[4 * k + 0] = pk2(v.x, v.x);
            qd1[4 * k + 1] = pk2(v.y, v.y);
            qd1[4 * k + 2] = pk2(v.z, v.z);
            qd1[4 * k + 3] = pk2(v.w, v.w);
        }
    }

    const ulonglong2* src =
        (const ulonglong2*)(g_cbp + ((size_t)h * NCP + cc * 512) * E);
    float best0 = -3.402823466e38f, best1 = -3.402823466e38f;
    int pb0 = 0, od0 = 0, pb1 = 0, od1 = 0;

    for (int sc = 0; sc < 4; ++sc) {
        __syncthreads();
#pragma unroll
        for (int j = 0; j < 8; ++j)       // coalesced 16 KB stage
            cbs[j * 128 + tid] = src[sc * 1024 + j * 128 + tid];
        __syncthreads();

        int pbase = sc * 128;             // pair index within this CTA's chunk
#pragma unroll 2
        for (int p = 0; p < 128; ++p) {   // warp-uniform -> broadcast LDS
            ulonglong2 c0 = cbs[p * 8 + 0];
            ulonglong2 c1 = cbs[p * 8 + 1];
            ulonglong2 c2 = cbs[p * 8 + 2];
            ulonglong2 c3 = cbs[p * 8 + 3];
            ulonglong2 c4 = cbs[p * 8 + 4];
            ulonglong2 c5 = cbs[p * 8 + 5];
            ulonglong2 c6 = cbs[p * 8 + 6];
            ulonglong2 c7 = cbs[p * 8 + 7];
            u64 a0 = 0ull, a1 = 0ull, a2 = 0ull, a3 = 0ull;
            u64 b0 = 0ull, b1 = 0ull, b2 = 0ull, b3 = 0ull;
            FMA2(a0, c0.x, qd0[0]);  FMA2(b0, c0.x, qd1[0]);
            FMA2(a1, c0.y, qd0[1]);  FMA2(b1, c0.y, qd1[1]);
            FMA2(a2, c1.x, qd0[2]);  FMA2(b2, c1.x, qd1[2]);
            FMA2(a3, c1.y, qd0[3]);  FMA2(b3, c1.y, qd1[3]);
            FMA2(a0, c2.x, qd0[4]);  FMA2(b0, c2.x, qd1[4]);
            FMA2(a1, c2.y, qd0[5]);  FMA2(b1, c2.y, qd1[5]);
            FMA2(a2, c3.x, qd0[6]);  FMA2(b2, c3.x, qd1[6]);
            FMA2(a3, c3.y, qd0[7]);  FMA2(b3, c3.y, qd1[7]);
            FMA2(a0, c4.x, qd0[8]);  FMA2(b0, c4.x, qd1[8]);
            FMA2(a1, c4.y, qd0[9]);  FMA2(b1, c4.y, qd1[9]);
            FMA2(a2, c5.x, qd0[10]); FMA2(b2, c5.x, qd1[10]);
            FMA2(a3, c5.y, qd0[11]); FMA2(b3, c5.y, qd1[11]);
            FMA2(a0, c6.x, qd0[12]); FMA2(b0, c6.x, qd1[12]);
            FMA2(a1, c6.y, qd0[13]); FMA2(b1, c6.y, qd1[13]);
            FMA2(a2, c7.x, qd0[14]); FMA2(b2, c7.x, qd1[14]);
            FMA2(a3, c7.y, qd0[15]); FMA2(b3, c7.y, qd1[15]);
            ADD2(a0, a0, a1); ADD2(a2, a2, a3); ADD2(a0, a0, a2);
            ADD2(b0, b0, b1); ADD2(b2, b2, b3); ADD2(b0, b0, b2);
            float s0, s1;
            upk2(s0, s1, a0);
            float m = fmaxf(s0, s1);
            if (m > best0) { best0 = m; pb0 = pbase + p; od0 = (s1 > s0); }
            upk2(s0, s1, b0);
            m = fmaxf(s0, s1);
            if (m > best1) { best1 = m; pb1 = pbase + p; od1 = (s1 > s0); }
        }
    }

    int base_code = cc * 1024;
    g_bestp[cc][(size_t)t0 * H + h]       = best0;
    g_idxp[cc][(size_t)t0 * H + h]        = base_code + 2 * pb0 + od0;
    g_bestp[cc][(size_t)(t0 + 1) * H + h] = best1;
    g_idxp[cc][(size_t)(t0 + 1) * H + h]  = base_code + 2 * pb1 + od1;
}

// -------- 6: merge the two code-chunk partials --------
// Tie -> chunk 0 (lower indices) = first-occurrence argmax semantics.
__global__ void reduce_kernel(float* __restrict__ out) {
    int i = blockIdx.x * 256 + threadIdx.x;   // 65536
    float b0 = g_bestp[0][i], b1 = g_bestp[1][i];
    int ix = (b1 > b0) ? g_idxp[1][i] : g_idxp[0][i];
    out[i] = (float)ix;
}

extern "C" void kernel_launch(void* const* d_in, const int* in_sizes, int n_in,
                              void* d_out, int out_size) {
    const float* x = nullptr;
    const float* W = nullptr;
    const float* CB = nullptr;
    for (int i = 0; i < n_in; ++i) {
        long s = (long)in_sizes[i];
        if (s == 8388608L || s == 33554432L)      x  = (const float*)d_in[i];
        else if (s == 131072L || s == 524288L)    W  = (const float*)d_in[i];
        else if (s == 262144L || s == 1048576L)   CB = (const float*)d_in[i];
    }
    if (!x || !W || !CB) {
        if (n_in >= 3) {
            x  = (const float*)d_in[0];
            W  = (const float*)d_in[1];
            CB = (const float*)d_in[2];
        }
    }
    prepS_kernel<<<128, 256>>>(W);
    prepW_kernel<<<256, 256>>>(W);
    prepCB_kernel<<<32, 256>>>(CB);
    proj_kernel<<<512, 128>>>(x);
    sim_kernel<<<512, 128>>>();
    reduce_kernel<<<256, 256>>>((float*)d_out);
}

// round 11
// speedup vs baseline: 1.4230x; 1.4230x over previous
#include <cuda_runtime.h>
#include <cstdint>

// Problem constants
#define TOK 8192      // b*n tokens
#define D   1024
#define H   8
#define E   16
#define CS  2048
#define COLS (H*E)     // 128 projection columns
#define CPAIR (COLS/2) // 64 column pairs
#define NCP (CS/2)     // 1024 code pairs per head

typedef unsigned long long u64;

// -------- device scratch (static; no allocations allowed) --------
__device__ float g_S[COLS];                           // column sums of W
__device__ __align__(16) float2 g_Wp[D * CPAIR];      // W' = W - S/D, [d][colpair]      (512 KB)
__device__ __align__(16) float2 g_cbp[H * NCP * E];   // normalized cb, code-pair packed (1 MB)
__device__ __align__(16) float  g_P[TOK * COLS];      // projections [t][h*16+e]         (4 MB)
__device__ float g_bestp[2][TOK * H];                 // partial argmax: best score
__device__ int   g_idxp[2][TOK * H];                  // partial argmax: index

// -------- f32x2 helpers --------
__device__ __forceinline__ u64 pk2(float lo, float hi) {
    u64 r; asm("mov.b64 %0, {%1,%2};" : "=l"(r) : "f"(lo), "f"(hi)); return r;
}
__device__ __forceinline__ void upk2(float& lo, float& hi, u64 v) {
    asm("mov.b64 {%0,%1}, %2;" : "=f"(lo), "=f"(hi) : "l"(v));
}
#define FMA2(acc, a, b) asm("fma.rn.f32x2 %0, %1, %2, %0;" : "+l"(acc) : "l"(a), "l"(b))
#define ADD2(d, a, b)   asm("add.rn.f32x2 %0, %1, %2;" : "=l"(d) : "l"(a), "l"(b))

// -------- 1: column sums S[h,e] = sum_d W[h,d,e] --------
__global__ void prepS_kernel(const float* __restrict__ W) {
    int col = blockIdx.x;            // h*16+e, 128 blocks
    int h = col >> 4, e = col & 15;
    float s = 0.f;
    for (int d = threadIdx.x; d < D; d += 256)
        s += W[(h * D + d) * E + e];
    __shared__ float red[256];
    red[threadIdx.x] = s;
    __syncthreads();
    for (int off = 128; off > 0; off >>= 1) {
        if (threadIdx.x < off) red[threadIdx.x] += red[threadIdx.x + off];
        __syncthreads();
    }
    if (threadIdx.x == 0) g_S[col] = red[0];
}

// -------- 2: W'[d][cp] = (W - S/D) packed as column-pairs --------
__global__ void prepW_kernel(const float* __restrict__ W) {
    int i = blockIdx.x * 256 + threadIdx.x;   // 65536 = D*CPAIR
    int d = i >> 6, cp = i & 63;
    int h = cp >> 3, ep = cp & 7;
    const float invD = 1.0f / 1024.0f;
    float w0 = W[(h * D + d) * E + 2 * ep]     - g_S[h * E + 2 * ep]     * invD;
    float w1 = W[(h * D + d) * E + 2 * ep + 1] - g_S[h * E + 2 * ep + 1] * invD;
    g_Wp[i] = make_float2(w0, w1);
}

// -------- 3: normalized codebook, code-pair packed --------
__global__ void prepCB_kernel(const float* __restrict__ CB) {
    int i = blockIdx.x * 256 + threadIdx.x;   // 8192 = H*NCP
    const float4* a4 = (const float4*)(CB + (size_t)i * 2 * E);
    float4 va[4], vb[4];
#pragma unroll
    for (int k = 0; k < 4; ++k) va[k] = a4[k];
#pragma unroll
    for (int k = 0; k < 4; ++k) vb[k] = a4[4 + k];
    float sa = 0.f, sb = 0.f;
#pragma unroll
    for (int k = 0; k < 4; ++k) {
        sa += va[k].x * va[k].x + va[k].y * va[k].y + va[k].z * va[k].z + va[k].w * va[k].w;
        sb += vb[k].x * vb[k].x + vb[k].y * vb[k].y + vb[k].z * vb[k].z + vb[k].w * vb[k].w;
    }
    float ra = 1.0f / sqrtf(sa + 1e-12f);
    float rb = 1.0f / sqrtf(sb + 1e-12f);
    float2* out = g_cbp + (size_t)i * E;
    const float* a = (const float*)va;
    const float* b = (const float*)vb;
#pragma unroll
    for (int e = 0; e < E; ++e)
        out[e] = make_float2(a[e] * ra, b[e] * rb);
}

// -------- 4: projection GEMM, f32x2, W broadcast / x per-lane -------------
// CTA: 128 thr, 32 tokens. lane = token; warp w owns colpairs 16w..16w+15.
// Per dd per thread: 1 LDS.32 (x) + 8 broadcast LDS.128 (W) + 16 FMA2.
__global__ __launch_bounds__(128) void proj_kernel(const float* __restrict__ x) {
    __shared__ float  xs[32][33];   // [tok][dd], 33-pad -> conflict-free column read
    __shared__ float2 Ws[32][64];   // [dd][colpair], 16 KB
    int t0 = blockIdx.x * 32;
    int tid = threadIdx.x;
    int lane = tid & 31;            // token within tile
    int w = tid >> 5;               // warp -> colpair group

    // staging addresses (constant across chunks)
    int xtok = tid >> 2;            // token staged (0..31)
    int xf4  = tid & 3;             // float4 slots xf4 and xf4+4 within 32-dd chunk
    const float4* xrow = (const float4*)(x + (size_t)(t0 + xtok) * D);

    u64 acc[16];
#pragma unroll
    for (int k = 0; k < 16; ++k) acc[k] = 0ull;

    float4 px0, px1;
    ulonglong2 pw[8];

    // prefetch chunk 0
    px0 = xrow[xf4];
    px1 = xrow[xf4 + 4];
#pragma unroll
    for (int j = 0; j < 8; ++j) {
        int q = j * 128 + tid;       // 0..1023
        int dd = q >> 5, c2 = q & 31;
        pw[j] = *(const ulonglong2*)&g_Wp[(size_t)dd * CPAIR + 2 * c2];
    }

    for (int ch = 0; ch < 32; ++ch) {
        if (ch > 0) __syncthreads();     // prev chunk consumed
        // store prefetched chunk
        {
            int d0 = 4 * xf4;
            xs[xtok][d0 + 0] = px0.x;
            xs[xtok][d0 + 1] = px0.y;
            xs[xtok][d0 + 2] = px0.z;
            xs[xtok][d0 + 3] = px0.w;
            xs[xtok][16 + d0 + 0] = px1.x;
            xs[xtok][16 + d0 + 1] = px1.y;
            xs[xtok][16 + d0 + 2] = px1.z;
            xs[xtok][16 + d0 + 3] = px1.w;
#pragma unroll
            for (int j = 0; j < 8; ++j) {
                int q = j * 128 + tid;
                int dd = q >> 5, c2 = q & 31;
                *(ulonglong2*)&Ws[dd][2 * c2] = pw[j];
            }
        }
        __syncthreads();
        // prefetch next chunk (hidden under compute)
        if (ch < 31) {
            int base = (ch + 1) * 32;
            px0 = xrow[(base >> 2) + xf4];
            px1 = xrow[(base >> 2) + xf4 + 4];
#pragma unroll
            for (int j = 0; j < 8; ++j) {
                int q = j * 128 + tid;
                int dd = q >> 5, c2 = q & 31;
                pw[j] = *(const ulonglong2*)&g_Wp[(size_t)(base + dd) * CPAIR + 2 * c2];
            }
        }
        // compute: per dd, x per-lane + W broadcast
#pragma unroll 4
        for (int dd = 0; dd < 32; ++dd) {
            float v = xs[lane][dd];
            u64 xv = pk2(v, v);
            const ulonglong2* wrow = (const ulonglong2*)&Ws[dd][16 * w];
#pragma unroll
            for (int j = 0; j < 8; ++j) {       // broadcast LDS.128
                ulonglong2 ww = wrow[j];
                FMA2(acc[2 * j],     ww.x, xv);
                FMA2(acc[2 * j + 1], ww.y, xv);
            }
        }
    }
    // write 32 columns for token (t0+lane), cols 32w..32w+31
    float* dst = &g_P[(size_t)(t0 + lane) * COLS + 32 * w];
#pragma unroll
    for (int j = 0; j < 4; ++j) {
        float4 o;
        upk2(o.x, o.y, acc[4 * j]);
        upk2(o.z, o.w, acc[4 * j + 1]);
        float4 o2;
        upk2(o2.x, o2.y, acc[4 * j + 2]);
        upk2(o2.z, o2.w, acc[4 * j + 3]);
        *(float4*)(dst + 8 * j) = o;
        *(float4*)(dst + 8 * j + 4) = o2;
    }
}

// -------- 5: similarity scan, code-chunk split, smem broadcast ------------
// Grid: 512 CTAs = 32 token-tiles x 8 heads x 2 code chunks. 128 thr, T=2.
// Per pair per token: 2 chains of 8 FMA2 + 1 ADD2 (34 fma-pipe ops / pair).
__global__ __launch_bounds__(128) void sim_kernel() {
    __shared__ ulonglong2 cbs[1024];      // 16 KB
    int tid = threadIdx.x;
    int b = blockIdx.x;
    int cc = b & 1;                       // code chunk (512 pairs)
    int h = (b >> 1) & 7;
    int tb = b >> 4;                      // 0..31
    int t0 = tb * 256 + tid * 2;

    u64 qd0[16], qd1[16];
    {
        const float4* q4 = (const float4*)&g_P[(size_t)t0 * COLS + h * E];
#pragma unroll
        for (int k = 0; k < 4; ++k) {
            float4 v = q4[k];
            qd0[4 * k + 0] = pk2(v.x, v.x);
            qd0[4 * k + 1] = pk2(v.y, v.y);
            qd0[4 * k + 2] = pk2(v.z, v.z);
            qd0[4 * k + 3] = pk2(v.w, v.w);
        }
        q4 = (const float4*)&g_P[(size_t)(t0 + 1) * COLS + h * E];
#pragma unroll
        for (int k = 0; k < 4; ++k) {
            float4 v = q4[k];
            qd1[4 * k + 0] = pk2(v.x, v.x);
            qd1[4 * k + 1] = pk2(v.y, v.y);
            qd1[4 * k + 2] = pk2(v.z, v.z);
            qd1[4 * k + 3] = pk2(v.w, v.w);
        }
    }

    const ulonglong2* src =
        (const ulonglong2*)(g_cbp + ((size_t)h * NCP + cc * 512) * E);
    float best0 = -3.402823466e38f, best1 = -3.402823466e38f;
    int pb0 = 0, od0 = 0, pb1 = 0, od1 = 0;

    for (int sc = 0; sc < 4; ++sc) {
        __syncthreads();
#pragma unroll
        for (int j = 0; j < 8; ++j)       // coalesced 16 KB stage
            cbs[j * 128 + tid] = src[sc * 1024 + j * 128 + tid];
        __syncthreads();

        int pbase = sc * 128;
#pragma unroll 4
        for (int p = 0; p < 128; ++p) {   // warp-uniform -> broadcast LDS
            ulonglong2 c0 = cbs[p * 8 + 0];
            ulonglong2 c1 = cbs[p * 8 + 1];
            ulonglong2 c2 = cbs[p * 8 + 2];
            ulonglong2 c3 = cbs[p * 8 + 3];
            ulonglong2 c4 = cbs[p * 8 + 4];
            ulonglong2 c5 = cbs[p * 8 + 5];
            ulonglong2 c6 = cbs[p * 8 + 6];
            ulonglong2 c7 = cbs[p * 8 + 7];
            u64 a0 = 0ull, a1 = 0ull;     // token 0: 2 chains (depth 8)
            u64 b0 = 0ull, b1 = 0ull;     // token 1: 2 chains
            FMA2(a0, c0.x, qd0[0]);  FMA2(b0, c0.x, qd1[0]);
            FMA2(a1, c0.y, qd0[1]);  FMA2(b1, c0.y, qd1[1]);
            FMA2(a0, c1.x, qd0[2]);  FMA2(b0, c1.x, qd1[2]);
            FMA2(a1, c1.y, qd0[3]);  FMA2(b1, c1.y, qd1[3]);
            FMA2(a0, c2.x, qd0[4]);  FMA2(b0, c2.x, qd1[4]);
            FMA2(a1, c2.y, qd0[5]);  FMA2(b1, c2.y, qd1[5]);
            FMA2(a0, c3.x, qd0[6]);  FMA2(b0, c3.x, qd1[6]);
            FMA2(a1, c3.y, qd0[7]);  FMA2(b1, c3.y, qd1[7]);
            FMA2(a0, c4.x, qd0[8]);  FMA2(b0, c4.x, qd1[8]);
            FMA2(a1, c4.y, qd0[9]);  FMA2(b1, c4.y, qd1[9]);
            FMA2(a0, c5.x, qd0[10]); FMA2(b0, c5.x, qd1[10]);
            FMA2(a1, c5.y, qd0[11]); FMA2(b1, c5.y, qd1[11]);
            FMA2(a0, c6.x, qd0[12]); FMA2(b0, c6.x, qd1[12]);
            FMA2(a1, c6.y, qd0[13]); FMA2(b1, c6.y, qd1[13]);
            FMA2(a0, c7.x, qd0[14]); FMA2(b0, c7.x, qd1[14]);
            FMA2(a1, c7.y, qd0[15]); FMA2(b1, c7.y, qd1[15]);
            ADD2(a0, a0, a1);
            ADD2(b0, b0, b1);
            float s0, s1;
            upk2(s0, s1, a0);
            float m = fmaxf(s0, s1);
            if (m > best0) { best0 = m; pb0 = pbase + p; od0 = (s1 > s0); }
            upk2(s0, s1, b0);
            m = fmaxf(s0, s1);
            if (m > best1) { best1 = m; pb1 = pbase + p; od1 = (s1 > s0); }
        }
    }

    int base_code = cc * 1024;
    g_bestp[cc][(size_t)t0 * H + h]       = best0;
    g_idxp[cc][(size_t)t0 * H + h]        = base_code + 2 * pb0 + od0;
    g_bestp[cc][(size_t)(t0 + 1) * H + h] = best1;
    g_idxp[cc][(size_t)(t0 + 1) * H + h]  = base_code + 2 * pb1 + od1;
}

// -------- 6: merge the two code-chunk partials --------
// Tie -> chunk 0 (lower indices) = first-occurrence argmax semantics.
__global__ void reduce_kernel(float* __restrict__ out) {
    int i = blockIdx.x * 256 + threadIdx.x;   // 65536
    float b0 = g_bestp[0][i], b1 = g_bestp[1][i];
    int ix = (b1 > b0) ? g_idxp[1][i] : g_idxp[0][i];
    out[i] = (float)ix;
}

extern "C" void kernel_launch(void* const* d_in, const int* in_sizes, int n_in,
                              void* d_out, int out_size) {
    const float* x = nullptr;
    const float* W = nullptr;
    const float* CB = nullptr;
    for (int i = 0; i < n_in; ++i) {
        long s = (long)in_sizes[i];
        if (s == 8388608L || s == 33554432L)      x  = (const float*)d_in[i];
        else if (s == 131072L || s == 524288L)    W  = (const float*)d_in[i];
        else if (s == 262144L || s == 1048576L)   CB = (const float*)d_in[i];
    }
    if (!x || !W || !CB) {
        if (n_in >= 3) {
            x  = (const float*)d_in[0];
            W  = (const float*)d_in[1];
            CB = (const float*)d_in[2];
        }
    }
    prepS_kernel<<<128, 256>>>(W);
    prepW_kernel<<<256, 256>>>(W);
    prepCB_kernel<<<32, 256>>>(CB);
    proj_kernel<<<256, 128>>>(x);
    sim_kernel<<<512, 128>>>();
    reduce_kernel<<<256, 256>>>((float*)d_out);
}

// round 12
// speedup vs baseline: 1.4372x; 1.0100x over previous
#include <cuda_runtime.h>
#include <cstdint>

// Problem constants
#define TOK 8192      // b*n tokens
#define D   1024
#define H   8
#define E   16
#define CS  2048
#define COLS (H*E)     // 128 projection columns
#define CPAIR (COLS/2) // 64 column pairs
#define NCP (CS/2)     // 1024 code pairs per head

typedef unsigned long long u64;

// -------- device scratch (static; no allocations allowed) --------
__device__ float g_S[COLS];                           // column sums of W
__device__ __align__(16) float2 g_Wp[D * CPAIR];      // W' = W - S/D, [d][colpair]      (512 KB)
__device__ __align__(16) float2 g_cbp[H * NCP * E];   // normalized cb, code-pair packed (1 MB)
__device__ __align__(16) float  g_Pp[2][TOK * COLS];  // projection halves (K-split)     (8 MB)
__device__ float g_bestp[2][TOK * H];                 // partial argmax: best score
__device__ int   g_idxp[2][TOK * H];                  // partial argmax: index

// -------- f32x2 helpers --------
__device__ __forceinline__ u64 pk2(float lo, float hi) {
    u64 r; asm("mov.b64 %0, {%1,%2};" : "=l"(r) : "f"(lo), "f"(hi)); return r;
}
__device__ __forceinline__ void upk2(float& lo, float& hi, u64 v) {
    asm("mov.b64 {%0,%1}, %2;" : "=f"(lo), "=f"(hi) : "l"(v));
}
#define FMA2(acc, a, b) asm("fma.rn.f32x2 %0, %1, %2, %0;" : "+l"(acc) : "l"(a), "l"(b))
#define ADD2(d, a, b)   asm("add.rn.f32x2 %0, %1, %2;" : "=l"(d) : "l"(a), "l"(b))

// -------- 1: column sums S[h,e] = sum_d W[h,d,e] --------
__global__ void prepS_kernel(const float* __restrict__ W) {
    int col = blockIdx.x;            // h*16+e, 128 blocks
    int h = col >> 4, e = col & 15;
    float s = 0.f;
    for (int d = threadIdx.x; d < D; d += 256)
        s += W[(h * D + d) * E + e];
    __shared__ float red[256];
    red[threadIdx.x] = s;
    __syncthreads();
    for (int off = 128; off > 0; off >>= 1) {
        if (threadIdx.x < off) red[threadIdx.x] += red[threadIdx.x + off];
        __syncthreads();
    }
    if (threadIdx.x == 0) g_S[col] = red[0];
}

// -------- 2: W'[d][cp] = (W - S/D) packed as column-pairs --------
__global__ void prepW_kernel(const float* __restrict__ W) {
    int i = blockIdx.x * 256 + threadIdx.x;   // 65536 = D*CPAIR
    int d = i >> 6, cp = i & 63;
    int h = cp >> 3, ep = cp & 7;
    const float invD = 1.0f / 1024.0f;
    float w0 = W[(h * D + d) * E + 2 * ep]     - g_S[h * E + 2 * ep]     * invD;
    float w1 = W[(h * D + d) * E + 2 * ep + 1] - g_S[h * E + 2 * ep + 1] * invD;
    g_Wp[i] = make_float2(w0, w1);
}

// -------- 3: normalized codebook, code-pair packed --------
__global__ void prepCB_kernel(const float* __restrict__ CB) {
    int i = blockIdx.x * 256 + threadIdx.x;   // 8192 = H*NCP
    const float4* a4 = (const float4*)(CB + (size_t)i * 2 * E);
    float4 va[4], vb[4];
#pragma unroll
    for (int k = 0; k < 4; ++k) va[k] = a4[k];
#pragma unroll
    for (int k = 0; k < 4; ++k) vb[k] = a4[4 + k];
    float sa = 0.f, sb = 0.f;
#pragma unroll
    for (int k = 0; k < 4; ++k) {
        sa += va[k].x * va[k].x + va[k].y * va[k].y + va[k].z * va[k].z + va[k].w * va[k].w;
        sb += vb[k].x * vb[k].x + vb[k].y * vb[k].y + vb[k].z * vb[k].z + vb[k].w * vb[k].w;
    }
    float ra = 1.0f / sqrtf(sa + 1e-12f);
    float rb = 1.0f / sqrtf(sb + 1e-12f);
    float2* out = g_cbp + (size_t)i * E;
    const float* a = (const float*)va;
    const float* b = (const float*)vb;
#pragma unroll
    for (int e = 0; e < E; ++e)
        out[e] = make_float2(a[e] * ra, b[e] * rb);
}

// -------- 4: projection GEMM, f32x2, K-split x2, 512 CTAs x 128 thr ------
// CTA (tile, half): 32 tokens x 64 colpairs over K=512. Thread (tg = tid&7,
// cg4 = tid>>3): tokens {tg,tg+8,tg+16,tg+24}, colpairs {4cg4..4cg4+3}.
// Per dd: 16 FMA2 : 6 LDS. Register-prefetch double buffering.
__global__ __launch_bounds__(128) void proj_kernel(const float* __restrict__ x) {
    __shared__ u64    xs[32][34];   // [tok][dd] dup (x,x); pad 34
    __shared__ float2 Ws[32][64];   // [dd][colpair], 16 KB
    int bb = blockIdx.x;
    int half = bb & 1;              // K-half: d in [512*half, 512*half+512)
    int t0 = (bb >> 1) * 32;
    int tid = threadIdx.x;
    int tg = tid & 7;
    int cg4 = tid >> 3;             // 0..15

    // staging addresses (constant across chunks)
    int xtok = tid >> 2;            // token staged by this thread (0..31)
    int xf4  = tid & 3;             // float4 slots xf4 and xf4+4 per 32-dd chunk
    const float4* xrow = (const float4*)(x + (size_t)(t0 + xtok) * D + half * 512);
    const float2* Wbase = g_Wp + (size_t)half * 512 * CPAIR;

    u64 acc[4][4];
#pragma unroll
    for (int i = 0; i < 4; ++i)
#pragma unroll
        for (int k = 0; k < 4; ++k) acc[i][k] = 0ull;

    float4 px0, px1;
    ulonglong2 pw[8];

    // prefetch chunk 0
    px0 = xrow[xf4];
    px1 = xrow[4 + xf4];
#pragma unroll
    for (int j = 0; j < 8; ++j) {
        int q = j * 128 + tid;       // 0..1023
        int dd = q >> 5, c2 = q & 31;
        pw[j] = *(const ulonglong2*)&Wbase[(size_t)dd * CPAIR + 2 * c2];
    }

    for (int ch = 0; ch < 16; ++ch) {
        if (ch > 0) __syncthreads();     // prev chunk consumed
        // store prefetched chunk
        {
            int d0 = 4 * xf4;
            xs[xtok][d0 + 0] = pk2(px0.x, px0.x);
            xs[xtok][d0 + 1] = pk2(px0.y, px0.y);
            xs[xtok][d0 + 2] = pk2(px0.z, px0.z);
            xs[xtok][d0 + 3] = pk2(px0.w, px0.w);
            xs[xtok][16 + d0 + 0] = pk2(px1.x, px1.x);
            xs[xtok][16 + d0 + 1] = pk2(px1.y, px1.y);
            xs[xtok][16 + d0 + 2] = pk2(px1.z, px1.z);
            xs[xtok][16 + d0 + 3] = pk2(px1.w, px1.w);
#pragma unroll
            for (int j = 0; j < 8; ++j) {
                int q = j * 128 + tid;
                int dd = q >> 5, c2 = q & 31;
                *(ulonglong2*)&Ws[dd][2 * c2] = pw[j];
            }
        }
        __syncthreads();
        // prefetch next chunk (hidden under compute)
        if (ch < 15) {
            int base = (ch + 1) * 32;
            px0 = xrow[(base >> 2) + xf4];
            px1 = xrow[(base >> 2) + 4 + xf4];
#pragma unroll
            for (int j = 0; j < 8; ++j) {
                int q = j * 128 + tid;
                int dd = q >> 5, c2 = q & 31;
                pw[j] = *(const ulonglong2*)&Wbase[(size_t)(base + dd) * CPAIR + 2 * c2];
            }
        }
        // compute
#pragma unroll 4
        for (int dd = 0; dd < 32; ++dd) {
            ulonglong2 w0 = *(const ulonglong2*)&Ws[dd][4 * cg4];
            ulonglong2 w1 = *(const ulonglong2*)&Ws[dd][4 * cg4 + 2];
#pragma unroll
            for (int i = 0; i < 4; ++i) {
                u64 xv = xs[tg + 8 * i][dd];
                FMA2(acc[i][0], w0.x, xv);
                FMA2(acc[i][1], w0.y, xv);
                FMA2(acc[i][2], w1.x, xv);
                FMA2(acc[i][3], w1.y, xv);
            }
        }
    }
#pragma unroll
    for (int i = 0; i < 4; ++i) {
        float4 o0, o1;
        upk2(o0.x, o0.y, acc[i][0]);
        upk2(o0.z, o0.w, acc[i][1]);
        upk2(o1.x, o1.y, acc[i][2]);
        upk2(o1.z, o1.w, acc[i][3]);
        float* dst = &g_Pp[half][(size_t)(t0 + tg + 8 * i) * COLS + 8 * cg4];
        *(float4*)dst = o0;
        *(float4*)(dst + 4) = o1;
    }
}

// -------- 5: similarity scan, T=1, 1024 CTAs x 128 thr --------------------
// Grid: 64 token-tiles (128 tok) x 8 heads x 2 code chunks. Each thread owns
// one (token, head) over 512 code pairs; q = g_Pp[0]+g_Pp[1] (K-split merge).
// Codebook in 4 sub-chunks of 128 pairs (16 KB smem), warp-uniform broadcast.
__global__ __launch_bounds__(128) void sim_kernel() {
    __shared__ ulonglong2 cbs[1024];      // 16 KB
    int tid = threadIdx.x;
    int b = blockIdx.x;
    int cc = b & 1;                       // code chunk (512 pairs)
    int h = (b >> 1) & 7;
    int tb = b >> 4;                      // 0..63
    int t = tb * 128 + tid;

    // q = P0 + P1, duplicated (16 u64)
    u64 qd[16];
    {
        const float4* qa = (const float4*)&g_Pp[0][(size_t)t * COLS + h * E];
        const float4* qb = (const float4*)&g_Pp[1][(size_t)t * COLS + h * E];
#pragma unroll
        for (int k = 0; k < 4; ++k) {
            float4 va = qa[k], vb = qb[k];
            float e0 = va.x + vb.x, e1 = va.y + vb.y;
            float e2 = va.z + vb.z, e3 = va.w + vb.w;
            qd[4 * k + 0] = pk2(e0, e0);
            qd[4 * k + 1] = pk2(e1, e1);
            qd[4 * k + 2] = pk2(e2, e2);
            qd[4 * k + 3] = pk2(e3, e3);
        }
    }

    const ulonglong2* src =
        (const ulonglong2*)(g_cbp + ((size_t)h * NCP + cc * 512) * E);
    float best = -3.402823466e38f;
    int pb = 0, od = 0;

    for (int sc = 0; sc < 4; ++sc) {
        __syncthreads();
#pragma unroll
        for (int j = 0; j < 8; ++j)       // coalesced 16 KB stage
            cbs[j * 128 + tid] = src[sc * 1024 + j * 128 + tid];
        __syncthreads();

        int pbase = sc * 128;
#pragma unroll 4
        for (int p = 0; p < 128; ++p) {   // warp-uniform -> broadcast LDS
            ulonglong2 c0 = cbs[p * 8 + 0];
            ulonglong2 c1 = cbs[p * 8 + 1];
            ulonglong2 c2 = cbs[p * 8 + 2];
            ulonglong2 c3 = cbs[p * 8 + 3];
            ulonglong2 c4 = cbs[p * 8 + 4];
            ulonglong2 c5 = cbs[p * 8 + 5];
            ulonglong2 c6 = cbs[p * 8 + 6];
            ulonglong2 c7 = cbs[p * 8 + 7];
            u64 a0 = 0ull, a1 = 0ull;     // 2 chains, depth 8
            FMA2(a0, c0.x, qd[0]);  FMA2(a1, c0.y, qd[1]);
            FMA2(a0, c1.x, qd[2]);  FMA2(a1, c1.y, qd[3]);
            FMA2(a0, c2.x, qd[4]);  FMA2(a1, c2.y, qd[5]);
            FMA2(a0, c3.x, qd[6]);  FMA2(a1, c3.y, qd[7]);
            FMA2(a0, c4.x, qd[8]);  FMA2(a1, c4.y, qd[9]);
            FMA2(a0, c5.x, qd[10]); FMA2(a1, c5.y, qd[11]);
            FMA2(a0, c6.x, qd[12]); FMA2(a1, c6.y, qd[13]);
            FMA2(a0, c7.x, qd[14]); FMA2(a1, c7.y, qd[15]);
            ADD2(a0, a0, a1);
            float s0, s1;
            upk2(s0, s1, a0);
            float m = fmaxf(s0, s1);
            if (m > best) { best = m; pb = pbase + p; od = (s1 > s0); }
        }
    }

    g_bestp[cc][(size_t)t * H + h] = best;
    g_idxp[cc][(size_t)t * H + h]  = cc * 1024 + 2 * pb + od;
}

// -------- 6: merge the two code-chunk partials --------
// Tie -> chunk 0 (lower indices) = first-occurrence argmax semantics.
__global__ void reduce_kernel(float* __restrict__ out) {
    int i = blockIdx.x * 256 + threadIdx.x;   // 65536
    float b0 = g_bestp[0][i], b1 = g_bestp[1][i];
    int ix = (b1 > b0) ? g_idxp[1][i] : g_idxp[0][i];
    out[i] = (float)ix;
}

extern "C" void kernel_launch(void* const* d_in, const int* in_sizes, int n_in,
                              void* d_out, int out_size) {
    const float* x = nullptr;
    const float* W = nullptr;
    const float* CB = nullptr;
    for (int i = 0; i < n_in; ++i) {
        long s = (long)in_sizes[i];
        if (s == 8388608L || s == 33554432L)      x  = (const float*)d_in[i];
        else if (s == 131072L || s == 524288L)    W  = (const float*)d_in[i];
        else if (s == 262144L || s == 1048576L)   CB = (const float*)d_in[i];
    }
    if (!x || !W || !CB) {
        if (n_in >= 3) {
            x  = (const float*)d_in[0];
            W  = (const float*)d_in[1];
            CB = (const float*)d_in[2];
        }
    }
    prepS_kernel<<<128, 256>>>(W);
    prepW_kernel<<<256, 256>>>(W);
    prepCB_kernel<<<32, 256>>>(CB);
    proj_kernel<<<512, 128>>>(x);
    sim_kernel<<<1024, 128>>>();
    reduce_kernel<<<256, 256>>>((float*)d_out);
}

// round 14
// speedup vs baseline: 1.4860x; 1.0340x over previous
#include <cuda_runtime.h>
#include <cstdint>

// Problem constants
#define TOK 8192      // b*n tokens
#define D   1024
#define H   8
#define E   16
#define CS  2048
#define COLS (H*E)     // 128 projection columns
#define CPAIR (COLS/2) // 64 column pairs
#define NCP (CS/2)     // 1024 code pairs per head

typedef unsigned long long u64;

// -------- device scratch (static; no allocations allowed) --------
__device__ float g_S[COLS];                           // column sums of W
__device__ __align__(16) float2 g_Wp[D * CPAIR];      // W' = W - S/D, [d][colpair]      (512 KB)
__device__ __align__(16) float2 g_cbp[H * NCP * E];   // normalized cb, code-pair packed (1 MB)
__device__ __align__(16) float  g_Pp[2][TOK * COLS];  // projection halves (K-split)     (8 MB)
__device__ float g_bestp[2][TOK * H];                 // partial argmax: best score
__device__ int   g_idxp[2][TOK * H];                  // partial argmax: index

// -------- f32x2 / async helpers --------
__device__ __forceinline__ u64 pk2(float lo, float hi) {
    u64 r; asm("mov.b64 %0, {%1,%2};" : "=l"(r) : "f"(lo), "f"(hi)); return r;
}
__device__ __forceinline__ void upk2(float& lo, float& hi, u64 v) {
    asm("mov.b64 {%0,%1}, %2;" : "=f"(lo), "=f"(hi) : "l"(v));
}
#define FMA2(acc, a, b) asm("fma.rn.f32x2 %0, %1, %2, %0;" : "+l"(acc) : "l"(a), "l"(b))
#define ADD2(d, a, b)   asm("add.rn.f32x2 %0, %1, %2;" : "=l"(d) : "l"(a), "l"(b))

__device__ __forceinline__ unsigned smem_u32(const void* p) {
    unsigned a;
    asm("{ .reg .u64 t; cvta.to.shared.u64 t, %1; cvt.u32.u64 %0, t; }"
        : "=r"(a) : "l"(p));
    return a;
}
#define CP16(dst, src) \
    asm volatile("cp.async.cg.shared.global [%0], [%1], 16;" :: "r"(dst), "l"(src))
#define CP_COMMIT() asm volatile("cp.async.commit_group;" ::: "memory")
#define CP_WAIT0()  asm volatile("cp.async.wait_group 0;" ::: "memory")

// -------- 1: column sums S[h,e] = sum_d W[h,d,e] --------
__global__ void prepS_kernel(const float* __restrict__ W) {
    int col = blockIdx.x;            // h*16+e, 128 blocks
    int h = col >> 4, e = col & 15;
    float s = 0.f;
    for (int d = threadIdx.x; d < D; d += 256)
        s += W[(h * D + d) * E + e];
    __shared__ float red[256];
    red[threadIdx.x] = s;
    __syncthreads();
    for (int off = 128; off > 0; off >>= 1) {
        if (threadIdx.x < off) red[threadIdx.x] += red[threadIdx.x + off];
        __syncthreads();
    }
    if (threadIdx.x == 0) g_S[col] = red[0];
}

// -------- 2: W'[d][cp] = (W - S/D) packed as column-pairs --------
__global__ void prepW_kernel(const float* __restrict__ W) {
    int i = blockIdx.x * 256 + threadIdx.x;   // 65536 = D*CPAIR
    int d = i >> 6, cp = i & 63;
    int h = cp >> 3, ep = cp & 7;
    const float invD = 1.0f / 1024.0f;
    float w0 = W[(h * D + d) * E + 2 * ep]     - g_S[h * E + 2 * ep]     * invD;
    float w1 = W[(h * D + d) * E + 2 * ep + 1] - g_S[h * E + 2 * ep + 1] * invD;
    g_Wp[i] = make_float2(w0, w1);
}

// -------- 3: normalized codebook, code-pair packed --------
__global__ void prepCB_kernel(const float* __restrict__ CB) {
    int i = blockIdx.x * 256 + threadIdx.x;   // 8192 = H*NCP
    const float4* a4 = (const float4*)(CB + (size_t)i * 2 * E);
    float4 va[4], vb[4];
#pragma unroll
    for (int k = 0; k < 4; ++k) va[k] = a4[k];
#pragma unroll
    for (int k = 0; k < 4; ++k) vb[k] = a4[4 + k];
    float sa = 0.f, sb = 0.f;
#pragma unroll
    for (int k = 0; k < 4; ++k) {
        sa += va[k].x * va[k].x + va[k].y * va[k].y + va[k].z * va[k].z + va[k].w * va[k].w;
        sb += vb[k].x * vb[k].x + vb[k].y * vb[k].y + vb[k].z * vb[k].z + vb[k].w * vb[k].w;
    }
    float ra = 1.0f / sqrtf(sa + 1e-12f);
    float rb = 1.0f / sqrtf(sb + 1e-12f);
    float2* out = g_cbp + (size_t)i * E;
    const float* a = (const float*)va;
    const float* b = (const float*)vb;
#pragma unroll
    for (int e = 0; e < E; ++e)
        out[e] = make_float2(a[e] * ra, b[e] * rb);
}

// -------- 4: projection GEMM, f32x2, cp.async double-buffered -------------
// Grid 512 = 256 token-tiles x 2 K-halves. CTA: 128 thr, 32 tok x 64 colpairs
// over K=512 (16 chunks of 32 dd). Thread (tg = tid&7, cg4 = tid>>3):
// tokens {tg,tg+8,tg+16,tg+24}, colpairs {4cg4..4cg4+3}. 16 FMA2 : 6 LDS / dd.
__global__ __launch_bounds__(128) void proj_kernel(const float* __restrict__ x) {
    __shared__ u64    xs[2][32][34];   // [buf][tok][dd] dup (x,x)
    __shared__ float2 Ws[2][32][64];   // [buf][dd][colpair], 16 KB each
    int bb = blockIdx.x;
    int half = bb & 1;
    int t0 = (bb >> 1) * 32;
    int tid = threadIdx.x;
    int tg = tid & 7;
    int cg4 = tid >> 3;

    int xtok = tid >> 2;               // token staged (0..31)
    int xf4  = tid & 3;                // float4 slots xf4, xf4+4 per chunk
    const float4* xrow = (const float4*)(x + (size_t)(t0 + xtok) * D + half * 512);
    const float2* Wbase = g_Wp + (size_t)half * 512 * CPAIR;

    u64 acc[4][4];
#pragma unroll
    for (int i = 0; i < 4; ++i)
#pragma unroll
        for (int k = 0; k < 4; ++k) acc[i][k] = 0ull;

    // per-thread staging slots for W (constant across chunks)
    int wdd[8], wc2[8];
#pragma unroll
    for (int j = 0; j < 8; ++j) {
        int q = j * 128 + tid;
        wdd[j] = q >> 5;
        wc2[j] = q & 31;
    }

    float4 px0, px1;

    // prologue: W0 async; x0 via regs -> xs[0]; x1 into regs
    px0 = xrow[xf4];
    px1 = xrow[4 + xf4];
#pragma unroll
    for (int j = 0; j < 8; ++j)
        CP16(smem_u32(&Ws[0][wdd[j]][2 * wc2[j]]),
             (const void*)&Wbase[(size_t)wdd[j] * CPAIR + 2 * wc2[j]]);
    CP_COMMIT();
    {
        int d0 = 4 * xf4;
        xs[0][xtok][d0 + 0] = pk2(px0.x, px0.x);
        xs[0][xtok][d0 + 1] = pk2(px0.y, px0.y);
        xs[0][xtok][d0 + 2] = pk2(px0.z, px0.z);
        xs[0][xtok][d0 + 3] = pk2(px0.w, px0.w);
        xs[0][xtok][16 + d0 + 0] = pk2(px1.x, px1.x);
        xs[0][xtok][16 + d0 + 1] = pk2(px1.y, px1.y);
        xs[0][xtok][16 + d0 + 2] = pk2(px1.z, px1.z);
        xs[0][xtok][16 + d0 + 3] = pk2(px1.w, px1.w);
    }
    px0 = xrow[8 + xf4];
    px1 = xrow[12 + xf4];
    CP_WAIT0();
    __syncthreads();

    for (int ch = 0; ch < 16; ++ch) {
        int buf = ch & 1;
        if (ch < 15) {
            int nb = buf ^ 1;
            // store x(ch+1) from regs into the idle buffer
            int d0 = 4 * xf4;
            xs[nb][xtok][d0 + 0] = pk2(px0.x, px0.x);
            xs[nb][xtok][d0 + 1] = pk2(px0.y, px0.y);
            xs[nb][xtok][d0 + 2] = pk2(px0.z, px0.z);
            xs[nb][xtok][d0 + 3] = pk2(px0.w, px0.w);
            xs[nb][xtok][16 + d0 + 0] = pk2(px1.x, px1.x);
            xs[nb][xtok][16 + d0 + 1] = pk2(px1.y, px1.y);
            xs[nb][xtok][16 + d0 + 2] = pk2(px1.z, px1.z);
            xs[nb][xtok][16 + d0 + 3] = pk2(px1.w, px1.w);
            // async W(ch+1) into idle buffer (overlaps compute below)
            const float2* wsrc = Wbase + (size_t)(ch + 1) * 32 * CPAIR;
#pragma unroll
            for (int j = 0; j < 8; ++j)
                CP16(smem_u32(&Ws[nb][wdd[j]][2 * wc2[j]]),
                     (const void*)&wsrc[(size_t)wdd[j] * CPAIR + 2 * wc2[j]]);
            CP_COMMIT();
            if (ch < 14) {                 // x(ch+2) into regs
                int f = (ch + 2) * 8;
                px0 = xrow[f + xf4];
                px1 = xrow[f + 4 + xf4];
            }
        }
        // compute chunk ch
#pragma unroll 4
        for (int dd = 0; dd < 32; ++dd) {
            ulonglong2 w0 = *(const ulonglong2*)&Ws[buf][dd][4 * cg4];
            ulonglong2 w1 = *(const ulonglong2*)&Ws[buf][dd][4 * cg4 + 2];
#pragma unroll
            for (int i = 0; i < 4; ++i) {
                u64 xv = xs[buf][tg + 8 * i][dd];
                FMA2(acc[i][0], w0.x, xv);
                FMA2(acc[i][1], w0.y, xv);
                FMA2(acc[i][2], w1.x, xv);
                FMA2(acc[i][3], w1.y, xv);
            }
        }
        if (ch < 15) {
            CP_WAIT0();
            __syncthreads();
        }
    }
#pragma unroll
    for (int i = 0; i < 4; ++i) {
        float4 o0, o1;
        upk2(o0.x, o0.y, acc[i][0]);
        upk2(o0.z, o0.w, acc[i][1]);
        upk2(o1.x, o1.y, acc[i][2]);
        upk2(o1.z, o1.w, acc[i][3]);
        float* dst = &g_Pp[half][(size_t)(t0 + tg + 8 * i) * COLS + 8 * cg4];
        *(float4*)dst = o0;
        *(float4*)(dst + 4) = o1;
    }
}

// -------- 5: similarity scan, cp.async double-buffered codebook -----------
// Grid: 1024 CTAs = 64 token-tiles x 8 heads x 2 code chunks. 128 thr, T=1.
// 8 sub-chunks of 64 pairs (8 KB x 2 buffers); pair idx warp-uniform ->
// broadcast LDS. q = g_Pp[0]+g_Pp[1] (K-split merge). 2 FMA2 chains depth 8.
__global__ __launch_bounds__(128) void sim_kernel() {
    __shared__ ulonglong2 cbs[2][512];    // 8 KB per buffer
    int tid = threadIdx.x;
    int b = blockIdx.x;
    int cc = b & 1;
    int h = (b >> 1) & 7;
    int tb = b >> 4;                      // 0..63
    int t = tb * 128 + tid;

    const ulonglong2* src =
        (const ulonglong2*)(g_cbp + ((size_t)h * NCP + cc * 512) * E);

    // stage sub-chunk 0 (async) while loading q
#pragma unroll
    for (int j = 0; j < 4; ++j) {
        int idx = j * 128 + tid;
        CP16(smem_u32(&cbs[0][idx]), (const void*)&src[idx]);
    }
    CP_COMMIT();

    // q = P0 + P1, duplicated (16 u64)
    u64 qd[16];
    {
        const float4* qa = (const float4*)&g_Pp[0][(size_t)t * COLS + h * E];
        const float4* qb = (const float4*)&g_Pp[1][(size_t)t * COLS + h * E];
#pragma unroll
        for (int k = 0; k < 4; ++k) {
            float4 va = qa[k], vb = qb[k];
            float e0 = va.x + vb.x, e1 = va.y + vb.y;
            float e2 = va.z + vb.z, e3 = va.w + vb.w;
            qd[4 * k + 0] = pk2(e0, e0);
            qd[4 * k + 1] = pk2(e1, e1);
            qd[4 * k + 2] = pk2(e2, e2);
            qd[4 * k + 3] = pk2(e3, e3);
        }
    }
    CP_WAIT0();
    __syncthreads();

    float best = -3.402823466e38f;
    int pb = 0, od = 0;

    for (int sc = 0; sc < 8; ++sc) {
        int buf = sc & 1;
        if (sc < 7) {                     // async stage sc+1 into idle buffer
            const ulonglong2* s2 = src + (size_t)(sc + 1) * 512;
#pragma unroll
            for (int j = 0; j < 4; ++j) {
                int idx = j * 128 + tid;
                CP16(smem_u32(&cbs[buf ^ 1][idx]), (const void*)&s2[idx]);
            }
            CP_COMMIT();
        }
        int pbase = sc * 64;
#pragma unroll 4
        for (int p = 0; p < 64; ++p) {    // warp-uniform -> broadcast LDS
            const ulonglong2* row = &cbs[buf][p * 8];
            ulonglong2 c0 = row[0];
            ulonglong2 c1 = row[1];
            ulonglong2 c2 = row[2];
            ulonglong2 c3 = row[3];
            ulonglong2 c4 = row[4];
            ulonglong2 c5 = row[5];
            ulonglong2 c6 = row[6];
            ulonglong2 c7 = row[7];
            u64 a0 = 0ull, a1 = 0ull;     // 2 chains, depth 8
            FMA2(a0, c0.x, qd[0]);  FMA2(a1, c0.y, qd[1]);
            FMA2(a0, c1.x, qd[2]);  FMA2(a1, c1.y, qd[3]);
            FMA2(a0, c2.x, qd[4]);  FMA2(a1, c2.y, qd[5]);
            FMA2(a0, c3.x, qd[6]);  FMA2(a1, c3.y, qd[7]);
            FMA2(a0, c4.x, qd[8]);  FMA2(a1, c4.y, qd[9]);
            FMA2(a0, c5.x, qd[10]); FMA2(a1, c5.y, qd[11]);
            FMA2(a0, c6.x, qd[12]); FMA2(a1, c6.y, qd[13]);
            FMA2(a0, c7.x, qd[14]); FMA2(a1, c7.y, qd[15]);
            ADD2(a0, a0, a1);
            float s0, s1;
            upk2(s0, s1, a0);
            float m = fmaxf(s0, s1);
            if (m > best) { best = m; pb = pbase + p; od = (s1 > s0); }
        }
        if (sc < 7) {
            CP_WAIT0();
            __syncthreads();
        }
    }

    g_bestp[cc][(size_t)t * H + h] = best;
    g_idxp[cc][(size_t)t * H + h]  = cc * 1024 + 2 * pb + od;
}

// -------- 6: merge the two code-chunk partials --------
// Tie -> chunk 0 (lower indices) = first-occurrence argmax semantics.
__global__ void reduce_kernel(float* __restrict__ out) {
    int i = blockIdx.x * 256 + threadIdx.x;   // 65536
    float b0 = g_bestp[0][i], b1 = g_bestp[1][i];
    int ix = (b1 > b0) ? g_idxp[1][i] : g_idxp[0][i];
    out[i] = (float)ix;
}

extern "C" void kernel_launch(void* const* d_in, const int* in_sizes, int n_in,
                              void* d_out, int out_size) {
    const float* x = nullptr;
    const float* W = nullptr;
    const float* CB = nullptr;
    for (int i = 0; i < n_in; ++i) {
        long s = (long)in_sizes[i];
        if (s == 8388608L || s == 33554432L)      x  = (const float*)d_in[i];
        else if (s == 131072L || s == 524288L)    W  = (const float*)d_in[i];
        else if (s == 262144L || s == 1048576L)   CB = (const float*)d_in[i];
    }
    if (!x || !W || !CB) {
        if (n_in >= 3) {
            x  = (const float*)d_in[0];
            W  = (const float*)d_in[1];
            CB = (const float*)d_in[2];
        }
    }
    prepS_kernel<<<128, 256>>>(W);
    prepW_kernel<<<256, 256>>>(W);
    prepCB_kernel<<<32, 256>>>(CB);
    proj_kernel<<<512, 128>>>(x);
    sim_kernel<<<1024, 128>>>();
    reduce_kernel<<<256, 256>>>((float*)d_out);
}